// round 15
// baseline (speedup 1.0000x reference)
#include <cuda_runtime.h>
#include <cuda_fp16.h>
#include <math.h>
#include <stdint.h>

#define BN_EPS 1e-5f
#define LOG2E 1.4426950408889634f

// ---------------- scratch (static device buffers; no allocations) ----------
__device__ __half g_kv  [64u*384u*784u];  // kv conv output (fp16) [b][o][n]
__device__ __half g_q   [64u*128u*196u];  // q  conv output (fp16) [b][o][n]
__device__ __half g_bias[ 8u*196u*784u];  // bias*log2e (fp16) [h][q][m]
__device__ __half g_att [64u*256u*196u];  // hardswish(attn out) (fp16) [b][c][n]

__device__ __forceinline__ float hardswish(float x) {
    float t = fminf(fmaxf(x + 3.f, 0.f), 6.f);
    return x * t * (1.f / 6.f);
}

__device__ __forceinline__ uint32_t pack_h2(float lo, float hi) {
    uint32_t r;
    asm("cvt.rn.f16x2.f32 %0, %1, %2;" : "=r"(r) : "f"(hi), "f"(lo));
    return r;
}

__device__ __forceinline__ uint32_t combine_h2(__half lo, __half hi) {
    return (uint32_t)__half_as_ushort(lo) | ((uint32_t)__half_as_ushort(hi) << 16);
}

__device__ __forceinline__ float exp2fast(float x) {
    float y;
    asm("ex2.approx.f32 %0, %1;" : "=f"(y) : "f"(x));
    return y;
}

__device__ __forceinline__ uint32_t h2exp2(uint32_t x) {
    uint32_t y;
    asm("ex2.approx.f16x2 %0, %1;" : "=r"(y) : "r"(x));
    return y;
}

__device__ __forceinline__ void mma_f16_k16(float c[4], const uint32_t a[4],
                                            uint32_t b0, uint32_t b1) {
    asm volatile(
        "mma.sync.aligned.m16n8k16.row.col.f32.f16.f16.f32 "
        "{%0,%1,%2,%3}, {%4,%5,%6,%7}, {%8,%9}, {%0,%1,%2,%3};"
        : "+f"(c[0]), "+f"(c[1]), "+f"(c[2]), "+f"(c[3])
        : "r"(a[0]), "r"(a[1]), "r"(a[2]), "r"(a[3]), "r"(b0), "r"(b1));
}

// fp16 accumulate (full-rate HMMA): C/D = 2 regs (4 halves)
__device__ __forceinline__ void mma_f16_k16_hacc(uint32_t c[2], const uint32_t a[4],
                                                 uint32_t b0, uint32_t b1) {
    asm volatile(
        "mma.sync.aligned.m16n8k16.row.col.f16.f16.f16.f16 "
        "{%0,%1}, {%2,%3,%4,%5}, {%6,%7}, {%0,%1};"
        : "+r"(c[0]), "+r"(c[1])
        : "r"(a[0]), "r"(a[1]), "r"(a[2]), "r"(a[3]), "r"(b0), "r"(b1));
}

__device__ __forceinline__ void mma_f16_k8(float c[4], uint32_t a0, uint32_t a1,
                                           uint32_t b0) {
    asm volatile(
        "mma.sync.aligned.m16n8k8.row.col.f32.f16.f16.f32 "
        "{%0,%1,%2,%3}, {%4,%5}, {%6}, {%0,%1,%2,%3};"
        : "+f"(c[0]), "+f"(c[1]), "+f"(c[2]), "+f"(c[3])
        : "r"(a0), "r"(a1), "r"(b0));
}

__device__ __forceinline__ float ld_in(const float* p)  { return *p; }
__device__ __forceinline__ float ld_in(const __half* p) { return __half2float(*p); }

__device__ __forceinline__ void st_pair(float* p, float y0, float y1) {
    *reinterpret_cast<float2*>(p) = make_float2(y0, y1);
}
__device__ __forceinline__ void st_pair(__half* p, float y0, float y1) {
    *reinterpret_cast<__half2*>(p) = __floats2half2_rn(y0, y1);
}

// pair permutation within groups of 8: phys = (p&3)*2 + (p>>2)
__device__ __forceinline__ int pperm(int p) { return ((p & 3) << 1) + (p >> 2); }

// ---------------- bias gather (half2 stores): g_bias[h][q][m] ---------------
__global__ void bias_gather_kernel(const float* __restrict__ ab,
                                   const int*   __restrict__ idxs,
                                   int n_off)
{
    int q = blockIdx.x;
    int h = blockIdx.y;
    int m = threadIdx.x * 2;   // 392 threads, 2 m each
    int i0 = idxs[q * 784 + m];
    int i1 = idxs[q * 784 + m + 1];
    __half2 v = __floats2half2_rn(ab[h * n_off + i0] * LOG2E,
                                  ab[h * n_off + i1] * LOG2E);
    *reinterpret_cast<__half2*>(&g_bias[((size_t)h * 196 + q) * 784 + m]) = v;
}

// ---------------- fp16 GEMM + BN + hardswish, batch-flattened N -------------
// ACC16: accumulate 4-slab groups (K=64) in f16 C fragments (full-rate HMMA),
// draining into f32 master accumulators every 4 slabs.
template<bool STRIDED, bool ACC16, typename IN_T, typename OUT_T>
__global__ void __launch_bounds__(256, 2)
conv_bn_hsw_tc_kernel(const IN_T* __restrict__ X, int xbs, int ldx,
                      const float* __restrict__ W, int C,
                      const float* __restrict__ gam, const float* __restrict__ bet,
                      const float* __restrict__ mu,  const float* __restrict__ var,
                      OUT_T* __restrict__ Y, int O, int NperB)
{
    __shared__ uint32_t As[2][128][10];
    __shared__ uint32_t Bs[2][128][10];

    const int o0 = blockIdx.x * 128;
    const int n0 = blockIdx.y * 128;
    const int t  = threadIdx.x;

    const int warp = t >> 5;
    const int lane = t & 31;
    const int g    = lane >> 2;
    const int t4   = lane & 3;
    const int wm   = warp >> 2;
    const int wn   = warp & 3;
    const int mrow0 = wm * 64;
    const int ncol0 = wn * 32;

    const int arow0 = t >> 2, aseg = t & 3;
    const int aph0 = pperm(2 * aseg), aph1 = pperm(2 * aseg + 1);
    const int bcol = t & 127;
    const int bks  = t >> 7;
    const int colg = n0 + bcol;
    const int bb   = colg / NperB;
    int nn = colg - bb * NperB;
    if (STRIDED) nn = 2 * (nn / 14) * 28 + 2 * (nn % 14);
    const IN_T* bsrc = X + (size_t)bb * xbs + nn;

    float acc[4][4][4];
    #pragma unroll
    for (int i = 0; i < 4; i++)
        #pragma unroll
        for (int j = 0; j < 4; j++)
            #pragma unroll
            for (int e = 0; e < 4; e++) acc[i][j][e] = 0.f;

    uint32_t hacc[4][4][2];
    if (ACC16) {
        #pragma unroll
        for (int i = 0; i < 4; i++)
            #pragma unroll
            for (int j = 0; j < 4; j++) { hacc[i][j][0] = 0u; hacc[i][j][1] = 0u; }
    }

    float4 avr[2];
    float  bvr[8];

    #pragma unroll
    for (int r = 0; r < 2; r++)
        avr[r] = *reinterpret_cast<const float4*>(&W[(o0 + arow0 + r * 64) * C + aseg * 4]);
    #pragma unroll
    for (int j = 0; j < 8; j++)
        bvr[j] = ld_in(bsrc + (size_t)(bks * 8 + j) * ldx);

    #pragma unroll
    for (int r = 0; r < 2; r++) {
        int row = arow0 + r * 64;
        As[0][row][aph0] = pack_h2(avr[r].x, avr[r].y);
        As[0][row][aph1] = pack_h2(avr[r].z, avr[r].w);
    }
    #pragma unroll
    for (int jj = 0; jj < 4; jj++)
        Bs[0][bcol][pperm(bks * 4 + jj)] = pack_h2(bvr[2 * jj], bvr[2 * jj + 1]);
    __syncthreads();

    int buf = 0;
    const int nslab = C >> 4;
    for (int s = 0; s < nslab; s++) {
        const bool more = (s + 1 < nslab);
        const int c1 = (s + 1) << 4;
        if (more) {
            #pragma unroll
            for (int r = 0; r < 2; r++)
                avr[r] = *reinterpret_cast<const float4*>(
                    &W[(o0 + arow0 + r * 64) * C + c1 + aseg * 4]);
            #pragma unroll
            for (int j = 0; j < 8; j++)
                bvr[j] = ld_in(bsrc + (size_t)(c1 + bks * 8 + j) * ldx);
        }

        {
            uint32_t a[4][4];
            #pragma unroll
            for (int mf = 0; mf < 4; mf++) {
                int rb = mrow0 + mf * 16;
                uint2 lo = *reinterpret_cast<const uint2*>(&As[buf][rb + g    ][2 * t4]);
                uint2 hi = *reinterpret_cast<const uint2*>(&As[buf][rb + g + 8][2 * t4]);
                a[mf][0] = lo.x; a[mf][1] = hi.x; a[mf][2] = lo.y; a[mf][3] = hi.y;
            }
            uint2 bfr[4];
            #pragma unroll
            for (int nf = 0; nf < 4; nf++)
                bfr[nf] = *reinterpret_cast<const uint2*>(&Bs[buf][ncol0 + nf * 8 + g][2 * t4]);
            #pragma unroll
            for (int mf = 0; mf < 4; mf++)
                #pragma unroll
                for (int nf = 0; nf < 4; nf++) {
                    if (ACC16)
                        mma_f16_k16_hacc(hacc[mf][nf], a[mf], bfr[nf].x, bfr[nf].y);
                    else
                        mma_f16_k16(acc[mf][nf], a[mf], bfr[nf].x, bfr[nf].y);
                }
        }

        // ---- drain f16 group accumulators into f32 masters every 4 slabs
        if (ACC16 && ((s & 3) == 3)) {
            #pragma unroll
            for (int mf = 0; mf < 4; mf++)
                #pragma unroll
                for (int nf = 0; nf < 4; nf++) {
                    float2 f0 = __half22float2(
                        *reinterpret_cast<__half2*>(&hacc[mf][nf][0]));
                    float2 f1 = __half22float2(
                        *reinterpret_cast<__half2*>(&hacc[mf][nf][1]));
                    acc[mf][nf][0] += f0.x; acc[mf][nf][1] += f0.y;
                    acc[mf][nf][2] += f1.x; acc[mf][nf][3] += f1.y;
                    hacc[mf][nf][0] = 0u;   hacc[mf][nf][1] = 0u;
                }
        }

        if (more) {
            int nb = buf ^ 1;
            #pragma unroll
            for (int r = 0; r < 2; r++) {
                int row = arow0 + r * 64;
                As[nb][row][aph0] = pack_h2(avr[r].x, avr[r].y);
                As[nb][row][aph1] = pack_h2(avr[r].z, avr[r].w);
            }
            #pragma unroll
            for (int jj = 0; jj < 4; jj++)
                Bs[nb][bcol][pperm(bks * 4 + jj)] = pack_h2(bvr[2 * jj], bvr[2 * jj + 1]);
        }
        __syncthreads();
        buf ^= 1;
    }

    int ecb[4]; int ecn[4];
    #pragma unroll
    for (int nf = 0; nf < 4; nf++) {
        int col = n0 + ncol0 + nf * 8 + t4 * 2;
        int cb2 = col / NperB;
        ecb[nf] = cb2;
        ecn[nf] = col - cb2 * NperB;
    }
    #pragma unroll
    for (int mf = 0; mf < 4; mf++) {
        #pragma unroll
        for (int half = 0; half < 2; half++) {
            int o = o0 + mrow0 + mf * 16 + g + half * 8;
            float sc = gam[o] * rsqrtf(var[o] + BN_EPS);
            float mm = mu[o], bt = bet[o];
            #pragma unroll
            for (int nf = 0; nf < 4; nf++) {
                float y0 = (acc[mf][nf][half * 2 + 0] - mm) * sc + bt;
                float y1 = (acc[mf][nf][half * 2 + 1] - mm) * sc + bt;
                st_pair(Y + ((size_t)ecb[nf] * O + o) * NperB + ecn[nf],
                        hardswish(y0), hardswish(y1));
            }
        }
    }
}

// ---------------- fp16 tensor-core flash attention (double-buffered) --------
// grid (512 bh, 2 qblocks), 256 threads / 8 warps, 16 queries per warp.
// Row-sum kept as per-thread partials; reduced once after the key loop.
__global__ void __launch_bounds__(256)
attention_tc_kernel()
{
    const int bh = blockIdx.x;
    const int b = bh >> 3, h = bh & 7;
    const int qb = blockIdx.y;
    const int t = threadIdx.x;
    const int warp = t >> 5, lane = t & 31;
    const int g = lane >> 2, t4 = lane & 3;

    __shared__ uint32_t Ks[2][56 * 8];    // [m][d-pair perm], pitch 8
    __shared__ uint32_t Vs[2][32 * 40];   // [d][m-pair perm], pitch 40

    const __half* kvb = g_kv + ((size_t)b * 384 + (size_t)h * 48) * 784;
    const __half* bsh = g_bias + (size_t)h * 196 * 784;

    const int kRow = t >> 3, kp = t & 7;
    const int kphys = pperm(kp);
    const __half* kp0 = kvb + (size_t)(2 * kp    ) * 784 + kRow;
    const __half* kp1 = kvb + (size_t)(2 * kp + 1) * 784 + kRow;
    const int vd = t >> 3, vl = t & 7;
    const __half* vrow = kvb + (size_t)(16 + vd) * 784;
    const bool kHi = (kRow < 24);

    const int q0 = qb * 128 + warp * 16;
    const int qA = q0 + g, qB = q0 + g + 8;

    uint32_t qh[4];
    {
        const float QS = 0.25f * LOG2E;
        float qa0 = 0.f, qa1 = 0.f, qa8 = 0.f, qa9 = 0.f;
        float qb0 = 0.f, qb1 = 0.f, qb8 = 0.f, qb9 = 0.f;
        const __half* qbase = g_q + (size_t)b * 128 * 196 + (size_t)h * 16 * 196;
        if (qA < 196) {
            qa0 = __half2float(qbase[(2 * t4    ) * 196 + qA]) * QS;
            qa1 = __half2float(qbase[(2 * t4 + 1) * 196 + qA]) * QS;
            qa8 = __half2float(qbase[(2 * t4 + 8) * 196 + qA]) * QS;
            qa9 = __half2float(qbase[(2 * t4 + 9) * 196 + qA]) * QS;
        }
        if (qB < 196) {
            qb0 = __half2float(qbase[(2 * t4    ) * 196 + qB]) * QS;
            qb1 = __half2float(qbase[(2 * t4 + 1) * 196 + qB]) * QS;
            qb8 = __half2float(qbase[(2 * t4 + 8) * 196 + qB]) * QS;
            qb9 = __half2float(qbase[(2 * t4 + 9) * 196 + qB]) * QS;
        }
        qh[0] = pack_h2(qa0, qa1);
        qh[1] = pack_h2(qb0, qb1);
        qh[2] = pack_h2(qa8, qa9);
        qh[3] = pack_h2(qb8, qb9);
    }

    float oc[4][4];
    #pragma unroll
    for (int v = 0; v < 4; v++)
        #pragma unroll
        for (int e = 0; e < 4; e++) oc[v][e] = 0.f;
    float rm0 = -1e30f, rm1 = -1e30f, rl0 = 0.f, rl1 = 0.f;

    __half ka0 = kp0[0], ka1 = kp1[0];
    __half kb0 = __float2half(0.f), kb1 = __float2half(0.f);
    if (kHi) { kb0 = kp0[32]; kb1 = kp1[32]; }
    uint32_t vreg[4];
    #pragma unroll
    for (int lp = 0; lp < 4; lp++) {
        int l = vl + 8 * lp;
        vreg[lp] = (l < 28) ? *reinterpret_cast<const uint32_t*>(vrow + 2 * l) : 0u;
    }
    Ks[0][kRow * 8 + kphys] = combine_h2(ka0, ka1);
    if (kHi) Ks[0][(kRow + 32) * 8 + kphys] = combine_h2(kb0, kb1);
    #pragma unroll
    for (int lp = 0; lp < 4; lp++) {
        int l = vl + 8 * lp;
        if (l < 28) Vs[0][vd * 40 + ((l >> 3) << 3) + pperm(l & 7)] = vreg[lp];
    }
    __syncthreads();

    int buf = 0;
    for (int c = 0; c < 14; c++) {
        const int m0 = c * 56;
        const bool more = (c + 1 < 14);
        const int m1 = m0 + 56;

        if (more) {
            ka0 = kp0[m1]; ka1 = kp1[m1];
            if (kHi) { kb0 = kp0[m1 + 32]; kb1 = kp1[m1 + 32]; }
            #pragma unroll
            for (int lp = 0; lp < 4; lp++) {
                int l = vl + 8 * lp;
                if (l < 28)
                    vreg[lp] = *reinterpret_cast<const uint32_t*>(vrow + m1 + 2 * l);
            }
        }

        float sc[7][4];
        #pragma unroll
        for (int j = 0; j < 7; j++) {
            int m = m0 + j * 8 + 2 * t4;
            if (qA < 196) {
                __half2 bv = *reinterpret_cast<const __half2*>(&bsh[(size_t)qA * 784 + m]);
                float2 bf = __half22float2(bv);
                sc[j][0] = bf.x; sc[j][1] = bf.y;
            } else { sc[j][0] = 0.f; sc[j][1] = 0.f; }
            if (qB < 196) {
                __half2 bv = *reinterpret_cast<const __half2*>(&bsh[(size_t)qB * 784 + m]);
                float2 bf = __half22float2(bv);
                sc[j][2] = bf.x; sc[j][3] = bf.y;
            } else { sc[j][2] = 0.f; sc[j][3] = 0.f; }
        }
        #pragma unroll
        for (int j = 0; j < 7; j++) {
            uint2 kk = *reinterpret_cast<const uint2*>(&Ks[buf][(j * 8 + g) * 8 + 2 * t4]);
            mma_f16_k16(sc[j], qh, kk.x, kk.y);
        }

        float mx0 = rm0, mx1 = rm1;
        #pragma unroll
        for (int j = 0; j < 7; j++) {
            mx0 = fmaxf(mx0, fmaxf(sc[j][0], sc[j][1]));
            mx1 = fmaxf(mx1, fmaxf(sc[j][2], sc[j][3]));
        }
        mx0 = fmaxf(mx0, __shfl_xor_sync(0xffffffffu, mx0, 1));
        mx0 = fmaxf(mx0, __shfl_xor_sync(0xffffffffu, mx0, 2));
        mx1 = fmaxf(mx1, __shfl_xor_sync(0xffffffffu, mx1, 1));
        mx1 = fmaxf(mx1, __shfl_xor_sync(0xffffffffu, mx1, 2));

        float a0 = exp2fast(rm0 - mx0), a1 = exp2fast(rm1 - mx1);
        rm0 = mx0; rm1 = mx1;
        #pragma unroll
        for (int v = 0; v < 4; v++) {
            oc[v][0] *= a0; oc[v][1] *= a0;
            oc[v][2] *= a1; oc[v][3] *= a1;
        }

        uint32_t ph[7][2];
        float s0 = 0.f, s1 = 0.f;
        #pragma unroll
        for (int j = 0; j < 7; j++) {
            uint32_t dA = pack_h2(sc[j][0] - mx0, sc[j][1] - mx0);
            uint32_t dB = pack_h2(sc[j][2] - mx1, sc[j][3] - mx1);
            uint32_t pA = h2exp2(dA);
            uint32_t pB = h2exp2(dB);
            ph[j][0] = pA;
            ph[j][1] = pB;
            float2 fA = __half22float2(*reinterpret_cast<__half2*>(&pA));
            float2 fB = __half22float2(*reinterpret_cast<__half2*>(&pB));
            s0 += fA.x + fA.y;
            s1 += fB.x + fB.y;
        }
        // per-thread partial row sums; reduced once after the loop
        rl0 = rl0 * a0 + s0;
        rl1 = rl1 * a1 + s1;

        #pragma unroll
        for (int jj = 0; jj < 3; jj++) {
            uint32_t pa[4] = { ph[2*jj][0], ph[2*jj][1], ph[2*jj+1][0], ph[2*jj+1][1] };
            #pragma unroll
            for (int v = 0; v < 4; v++) {
                uint2 vv = *reinterpret_cast<const uint2*>(
                    &Vs[buf][(v * 8 + g) * 40 + 8 * jj + 2 * t4]);
                mma_f16_k16(oc[v], pa, vv.x, vv.y);
            }
        }
        #pragma unroll
        for (int v = 0; v < 4; v++) {
            uint32_t vv = Vs[buf][(v * 8 + g) * 40 + 24 + 2 * t4];
            mma_f16_k8(oc[v], ph[6][0], ph[6][1], vv);
        }

        if (more) {
            int nb = buf ^ 1;
            Ks[nb][kRow * 8 + kphys] = combine_h2(ka0, ka1);
            if (kHi) Ks[nb][(kRow + 32) * 8 + kphys] = combine_h2(kb0, kb1);
            #pragma unroll
            for (int lp = 0; lp < 4; lp++) {
                int l = vl + 8 * lp;
                if (l < 28) Vs[nb][vd * 40 + ((l >> 3) << 3) + pperm(l & 7)] = vreg[lp];
            }
            __syncthreads();
        }
        buf ^= 1;
    }

    // final row-sum reduction (once, instead of per chunk)
    rl0 += __shfl_xor_sync(0xffffffffu, rl0, 1);
    rl0 += __shfl_xor_sync(0xffffffffu, rl0, 2);
    rl1 += __shfl_xor_sync(0xffffffffu, rl1, 1);
    rl1 += __shfl_xor_sync(0xffffffffu, rl1, 2);

    float inv0 = 1.f / rl0, inv1 = 1.f / rl1;
    #pragma unroll
    for (int v = 0; v < 4; v++) {
        #pragma unroll
        for (int e = 0; e < 2; e++) {
            int d = v * 8 + 2 * t4 + e;
            if (qA < 196)
                g_att[((size_t)b * 256 + h * 32 + d) * 196 + qA] =
                    __float2half(hardswish(oc[v][e] * inv0));
            if (qB < 196)
                g_att[((size_t)b * 256 + h * 32 + d) * 196 + qB] =
                    __float2half(hardswish(oc[v][2 + e] * inv1));
        }
    }
}

// ---------------- launch -----------------------------------------------------
extern "C" void kernel_launch(void* const* d_in, const int* in_sizes, int n_in,
                              void* d_out, int out_size)
{
    const float* x      = (const float*)d_in[0];
    const float* kv_w   = (const float*)d_in[1];
    const float* kv_g   = (const float*)d_in[2];
    const float* kv_b   = (const float*)d_in[3];
    const float* kv_m   = (const float*)d_in[4];
    const float* kv_v   = (const float*)d_in[5];
    const float* q_w    = (const float*)d_in[6];
    const float* q_g    = (const float*)d_in[7];
    const float* q_b    = (const float*)d_in[8];
    const float* q_m    = (const float*)d_in[9];
    const float* q_v    = (const float*)d_in[10];
    const float* proj_w = (const float*)d_in[11];
    const float* proj_g = (const float*)d_in[12];
    const float* proj_b = (const float*)d_in[13];
    const float* proj_m = (const float*)d_in[14];
    const float* proj_v = (const float*)d_in[15];
    const float* ab     = (const float*)d_in[16];
    const int*   idxs   = (const int*)  d_in[17];
    const int n_off = in_sizes[16] / 8;

    float* out = (float*)d_out;

    __half *p_kv, *p_q, *p_att;
    cudaGetSymbolAddress((void**)&p_kv,  g_kv);
    cudaGetSymbolAddress((void**)&p_q,   g_q);
    cudaGetSymbolAddress((void**)&p_att, g_att);

    // side stream + events (created once; host objects, no device allocations)
    static cudaStream_t s1 = nullptr;
    static cudaEvent_t evFork = nullptr, evJoin = nullptr;
    if (s1 == nullptr) {
        cudaStreamCreateWithFlags(&s1, cudaStreamNonBlocking);
        cudaEventCreateWithFlags(&evFork, cudaEventDisableTiming);
        cudaEventCreateWithFlags(&evJoin, cudaEventDisableTiming);
    }

    // ---- fork: gather + q GEMM on s1, kv GEMM on the main (capture) stream
    cudaEventRecord(evFork, 0);
    cudaStreamWaitEvent(s1, evFork, 0);

    bias_gather_kernel<<<dim3(196, 8), 392, 0, s1>>>(ab, idxs, n_off);
    conv_bn_hsw_tc_kernel<true, true, float, __half><<<dim3(1, 98), 256, 0, s1>>>(
        x, 256 * 784, 784, q_w, 256, q_g, q_b, q_m, q_v, p_q, 128, 196);
    cudaEventRecord(evJoin, s1);

    conv_bn_hsw_tc_kernel<false, true, float, __half><<<dim3(3, 392), 256>>>(
        x, 256 * 784, 784, kv_w, 256, kv_g, kv_b, kv_m, kv_v, p_kv, 384, 784);

    // ---- join, then attention + proj on the main stream
    cudaStreamWaitEvent(0, evJoin, 0);

    attention_tc_kernel<<<dim3(512, 2), 256>>>();

    conv_bn_hsw_tc_kernel<false, false, __half, float><<<dim3(4, 98), 256>>>(
        p_att, 256 * 196, 196, proj_w, 256, proj_g, proj_b, proj_m, proj_v, out, 512, 196);
}

// round 16
// speedup vs baseline: 1.1203x; 1.1203x over previous
#include <cuda_runtime.h>
#include <cuda_fp16.h>
#include <math.h>
#include <stdint.h>

#define BN_EPS 1e-5f
#define LOG2E 1.4426950408889634f

// ---------------- scratch (static device buffers; no allocations) ----------
__device__ __half g_kv  [64u*384u*784u];  // kv conv output (fp16) [b][o][n]
__device__ __half g_q   [64u*128u*196u];  // q  conv output (fp16) [b][o][n]
__device__ __half g_bias[ 8u*196u*784u];  // bias*log2e (fp16) [h][q][m]
__device__ __half g_att [64u*256u*196u];  // hardswish(attn out) (fp16) [b][c][n]

__device__ __forceinline__ float hardswish(float x) {
    float t = fminf(fmaxf(x + 3.f, 0.f), 6.f);
    return x * t * (1.f / 6.f);
}

__device__ __forceinline__ uint32_t pack_h2(float lo, float hi) {
    uint32_t r;
    asm("cvt.rn.f16x2.f32 %0, %1, %2;" : "=r"(r) : "f"(hi), "f"(lo));
    return r;
}

__device__ __forceinline__ uint32_t combine_h2(__half lo, __half hi) {
    return (uint32_t)__half_as_ushort(lo) | ((uint32_t)__half_as_ushort(hi) << 16);
}

__device__ __forceinline__ float exp2fast(float x) {
    float y;
    asm("ex2.approx.f32 %0, %1;" : "=f"(y) : "f"(x));
    return y;
}

__device__ __forceinline__ uint32_t h2exp2(uint32_t x) {
    uint32_t y;
    asm("ex2.approx.f16x2 %0, %1;" : "=r"(y) : "r"(x));
    return y;
}

__device__ __forceinline__ uint32_t hmax2(uint32_t a, uint32_t b) {
    uint32_t r;
    asm("max.f16x2 %0, %1, %2;" : "=r"(r) : "r"(a), "r"(b));
    return r;
}

__device__ __forceinline__ void mma_f16_k16(float c[4], const uint32_t a[4],
                                            uint32_t b0, uint32_t b1) {
    asm volatile(
        "mma.sync.aligned.m16n8k16.row.col.f32.f16.f16.f32 "
        "{%0,%1,%2,%3}, {%4,%5,%6,%7}, {%8,%9}, {%0,%1,%2,%3};"
        : "+f"(c[0]), "+f"(c[1]), "+f"(c[2]), "+f"(c[3])
        : "r"(a[0]), "r"(a[1]), "r"(a[2]), "r"(a[3]), "r"(b0), "r"(b1));
}

__device__ __forceinline__ void mma_f16_k8(float c[4], uint32_t a0, uint32_t a1,
                                           uint32_t b0) {
    asm volatile(
        "mma.sync.aligned.m16n8k8.row.col.f32.f16.f16.f32 "
        "{%0,%1,%2,%3}, {%4,%5}, {%6}, {%0,%1,%2,%3};"
        : "+f"(c[0]), "+f"(c[1]), "+f"(c[2]), "+f"(c[3])
        : "r"(a0), "r"(a1), "r"(b0));
}

__device__ __forceinline__ float ld_in(const float* p)  { return *p; }
__device__ __forceinline__ float ld_in(const __half* p) { return __half2float(*p); }

__device__ __forceinline__ void st_pair(float* p, float y0, float y1) {
    *reinterpret_cast<float2*>(p) = make_float2(y0, y1);
}
__device__ __forceinline__ void st_pair(__half* p, float y0, float y1) {
    *reinterpret_cast<__half2*>(p) = __floats2half2_rn(y0, y1);
}

// pair permutation within groups of 8: phys = (p&3)*2 + (p>>2)
__device__ __forceinline__ int pperm(int p) { return ((p & 3) << 1) + (p >> 2); }

// ---------------- bias gather (half2 stores): g_bias[h][q][m] ---------------
__global__ void bias_gather_kernel(const float* __restrict__ ab,
                                   const int*   __restrict__ idxs,
                                   int n_off)
{
    int q = blockIdx.x;
    int h = blockIdx.y;
    int m = threadIdx.x * 2;   // 392 threads, 2 m each
    int i0 = idxs[q * 784 + m];
    int i1 = idxs[q * 784 + m + 1];
    __half2 v = __floats2half2_rn(ab[h * n_off + i0] * LOG2E,
                                  ab[h * n_off + i1] * LOG2E);
    *reinterpret_cast<__half2*>(&g_bias[((size_t)h * 196 + q) * 784 + m]) = v;
}

// ---------------- fp16 GEMM + BN + hardswish, batch-flattened N -------------
template<bool STRIDED, typename IN_T, typename OUT_T>
__global__ void __launch_bounds__(256, 2)
conv_bn_hsw_tc_kernel(const IN_T* __restrict__ X, int xbs, int ldx,
                      const float* __restrict__ W, int C,
                      const float* __restrict__ gam, const float* __restrict__ bet,
                      const float* __restrict__ mu,  const float* __restrict__ var,
                      OUT_T* __restrict__ Y, int O, int NperB)
{
    __shared__ uint32_t As[2][128][10];
    __shared__ uint32_t Bs[2][128][10];

    const int o0 = blockIdx.x * 128;
    const int n0 = blockIdx.y * 128;
    const int t  = threadIdx.x;

    const int warp = t >> 5;
    const int lane = t & 31;
    const int g    = lane >> 2;
    const int t4   = lane & 3;
    const int wm   = warp >> 2;
    const int wn   = warp & 3;
    const int mrow0 = wm * 64;
    const int ncol0 = wn * 32;

    const int arow0 = t >> 2, aseg = t & 3;
    const int aph0 = pperm(2 * aseg), aph1 = pperm(2 * aseg + 1);
    const int bcol = t & 127;
    const int bks  = t >> 7;
    const int colg = n0 + bcol;
    const int bb   = colg / NperB;
    int nn = colg - bb * NperB;
    if (STRIDED) nn = 2 * (nn / 14) * 28 + 2 * (nn % 14);
    const IN_T* bsrc = X + (size_t)bb * xbs + nn;

    float acc[4][4][4];
    #pragma unroll
    for (int i = 0; i < 4; i++)
        #pragma unroll
        for (int j = 0; j < 4; j++)
            #pragma unroll
            for (int e = 0; e < 4; e++) acc[i][j][e] = 0.f;

    float4 avr[2];
    float  bvr[8];

    #pragma unroll
    for (int r = 0; r < 2; r++)
        avr[r] = *reinterpret_cast<const float4*>(&W[(o0 + arow0 + r * 64) * C + aseg * 4]);
    #pragma unroll
    for (int j = 0; j < 8; j++)
        bvr[j] = ld_in(bsrc + (size_t)(bks * 8 + j) * ldx);

    #pragma unroll
    for (int r = 0; r < 2; r++) {
        int row = arow0 + r * 64;
        As[0][row][aph0] = pack_h2(avr[r].x, avr[r].y);
        As[0][row][aph1] = pack_h2(avr[r].z, avr[r].w);
    }
    #pragma unroll
    for (int jj = 0; jj < 4; jj++)
        Bs[0][bcol][pperm(bks * 4 + jj)] = pack_h2(bvr[2 * jj], bvr[2 * jj + 1]);
    __syncthreads();

    int buf = 0;
    const int nslab = C >> 4;
    for (int s = 0; s < nslab; s++) {
        const bool more = (s + 1 < nslab);
        const int c1 = (s + 1) << 4;
        if (more) {
            #pragma unroll
            for (int r = 0; r < 2; r++)
                avr[r] = *reinterpret_cast<const float4*>(
                    &W[(o0 + arow0 + r * 64) * C + c1 + aseg * 4]);
            #pragma unroll
            for (int j = 0; j < 8; j++)
                bvr[j] = ld_in(bsrc + (size_t)(c1 + bks * 8 + j) * ldx);
        }

        {
            uint32_t a[4][4];
            #pragma unroll
            for (int mf = 0; mf < 4; mf++) {
                int rb = mrow0 + mf * 16;
                uint2 lo = *reinterpret_cast<const uint2*>(&As[buf][rb + g    ][2 * t4]);
                uint2 hi = *reinterpret_cast<const uint2*>(&As[buf][rb + g + 8][2 * t4]);
                a[mf][0] = lo.x; a[mf][1] = hi.x; a[mf][2] = lo.y; a[mf][3] = hi.y;
            }
            uint2 bfr[4];
            #pragma unroll
            for (int nf = 0; nf < 4; nf++)
                bfr[nf] = *reinterpret_cast<const uint2*>(&Bs[buf][ncol0 + nf * 8 + g][2 * t4]);
            #pragma unroll
            for (int mf = 0; mf < 4; mf++)
                #pragma unroll
                for (int nf = 0; nf < 4; nf++)
                    mma_f16_k16(acc[mf][nf], a[mf], bfr[nf].x, bfr[nf].y);
        }

        if (more) {
            int nb = buf ^ 1;
            #pragma unroll
            for (int r = 0; r < 2; r++) {
                int row = arow0 + r * 64;
                As[nb][row][aph0] = pack_h2(avr[r].x, avr[r].y);
                As[nb][row][aph1] = pack_h2(avr[r].z, avr[r].w);
            }
            #pragma unroll
            for (int jj = 0; jj < 4; jj++)
                Bs[nb][bcol][pperm(bks * 4 + jj)] = pack_h2(bvr[2 * jj], bvr[2 * jj + 1]);
        }
        __syncthreads();
        buf ^= 1;
    }

    int ecb[4]; int ecn[4];
    #pragma unroll
    for (int nf = 0; nf < 4; nf++) {
        int col = n0 + ncol0 + nf * 8 + t4 * 2;
        int cb2 = col / NperB;
        ecb[nf] = cb2;
        ecn[nf] = col - cb2 * NperB;
    }
    #pragma unroll
    for (int mf = 0; mf < 4; mf++) {
        #pragma unroll
        for (int half = 0; half < 2; half++) {
            int o = o0 + mrow0 + mf * 16 + g + half * 8;
            float sc = gam[o] * rsqrtf(var[o] + BN_EPS);
            float mm = mu[o], bt = bet[o];
            #pragma unroll
            for (int nf = 0; nf < 4; nf++) {
                float y0 = (acc[mf][nf][half * 2 + 0] - mm) * sc + bt;
                float y1 = (acc[mf][nf][half * 2 + 1] - mm) * sc + bt;
                st_pair(Y + ((size_t)ecb[nf] * O + o) * NperB + ecn[nf],
                        hardswish(y0), hardswish(y1));
            }
        }
    }
}

// ---------------- fp16 tensor-core flash attention (double-buffered) --------
// grid (512 bh, 2 qblocks), 256 threads / 8 warps, 16 queries per warp.
// Row-max reduced via packed fp16x2 shuffles (2 shuffles instead of 4).
__global__ void __launch_bounds__(256)
attention_tc_kernel()
{
    const int bh = blockIdx.x;
    const int b = bh >> 3, h = bh & 7;
    const int qb = blockIdx.y;
    const int t = threadIdx.x;
    const int warp = t >> 5, lane = t & 31;
    const int g = lane >> 2, t4 = lane & 3;

    __shared__ uint32_t Ks[2][56 * 8];    // [m][d-pair perm], pitch 8
    __shared__ uint32_t Vs[2][32 * 40];   // [d][m-pair perm], pitch 40

    const __half* kvb = g_kv + ((size_t)b * 384 + (size_t)h * 48) * 784;
    const __half* bsh = g_bias + (size_t)h * 196 * 784;

    const int kRow = t >> 3, kp = t & 7;
    const int kphys = pperm(kp);
    const __half* kp0 = kvb + (size_t)(2 * kp    ) * 784 + kRow;
    const __half* kp1 = kvb + (size_t)(2 * kp + 1) * 784 + kRow;
    const int vd = t >> 3, vl = t & 7;
    const __half* vrow = kvb + (size_t)(16 + vd) * 784;
    const bool kHi = (kRow < 24);

    const int q0 = qb * 128 + warp * 16;
    const int qA = q0 + g, qB = q0 + g + 8;

    uint32_t qh[4];
    {
        const float QS = 0.25f * LOG2E;
        float qa0 = 0.f, qa1 = 0.f, qa8 = 0.f, qa9 = 0.f;
        float qb0 = 0.f, qb1 = 0.f, qb8 = 0.f, qb9 = 0.f;
        const __half* qbase = g_q + (size_t)b * 128 * 196 + (size_t)h * 16 * 196;
        if (qA < 196) {
            qa0 = __half2float(qbase[(2 * t4    ) * 196 + qA]) * QS;
            qa1 = __half2float(qbase[(2 * t4 + 1) * 196 + qA]) * QS;
            qa8 = __half2float(qbase[(2 * t4 + 8) * 196 + qA]) * QS;
            qa9 = __half2float(qbase[(2 * t4 + 9) * 196 + qA]) * QS;
        }
        if (qB < 196) {
            qb0 = __half2float(qbase[(2 * t4    ) * 196 + qB]) * QS;
            qb1 = __half2float(qbase[(2 * t4 + 1) * 196 + qB]) * QS;
            qb8 = __half2float(qbase[(2 * t4 + 8) * 196 + qB]) * QS;
            qb9 = __half2float(qbase[(2 * t4 + 9) * 196 + qB]) * QS;
        }
        qh[0] = pack_h2(qa0, qa1);
        qh[1] = pack_h2(qb0, qb1);
        qh[2] = pack_h2(qa8, qa9);
        qh[3] = pack_h2(qb8, qb9);
    }

    float oc[4][4];
    #pragma unroll
    for (int v = 0; v < 4; v++)
        #pragma unroll
        for (int e = 0; e < 4; e++) oc[v][e] = 0.f;
    float rm0 = -1e4f, rm1 = -1e4f, rl0 = 0.f, rl1 = 0.f;

    __half ka0 = kp0[0], ka1 = kp1[0];
    __half kb0 = __float2half(0.f), kb1 = __float2half(0.f);
    if (kHi) { kb0 = kp0[32]; kb1 = kp1[32]; }
    uint32_t vreg[4];
    #pragma unroll
    for (int lp = 0; lp < 4; lp++) {
        int l = vl + 8 * lp;
        vreg[lp] = (l < 28) ? *reinterpret_cast<const uint32_t*>(vrow + 2 * l) : 0u;
    }
    Ks[0][kRow * 8 + kphys] = combine_h2(ka0, ka1);
    if (kHi) Ks[0][(kRow + 32) * 8 + kphys] = combine_h2(kb0, kb1);
    #pragma unroll
    for (int lp = 0; lp < 4; lp++) {
        int l = vl + 8 * lp;
        if (l < 28) Vs[0][vd * 40 + ((l >> 3) << 3) + pperm(l & 7)] = vreg[lp];
    }
    __syncthreads();

    int buf = 0;
    for (int c = 0; c < 14; c++) {
        const int m0 = c * 56;
        const bool more = (c + 1 < 14);
        const int m1 = m0 + 56;

        if (more) {
            ka0 = kp0[m1]; ka1 = kp1[m1];
            if (kHi) { kb0 = kp0[m1 + 32]; kb1 = kp1[m1 + 32]; }
            #pragma unroll
            for (int lp = 0; lp < 4; lp++) {
                int l = vl + 8 * lp;
                if (l < 28)
                    vreg[lp] = *reinterpret_cast<const uint32_t*>(vrow + m1 + 2 * l);
            }
        }

        float sc[7][4];
        #pragma unroll
        for (int j = 0; j < 7; j++) {
            int m = m0 + j * 8 + 2 * t4;
            if (qA < 196) {
                __half2 bv = *reinterpret_cast<const __half2*>(&bsh[(size_t)qA * 784 + m]);
                float2 bf = __half22float2(bv);
                sc[j][0] = bf.x; sc[j][1] = bf.y;
            } else { sc[j][0] = 0.f; sc[j][1] = 0.f; }
            if (qB < 196) {
                __half2 bv = *reinterpret_cast<const __half2*>(&bsh[(size_t)qB * 784 + m]);
                float2 bf = __half22float2(bv);
                sc[j][2] = bf.x; sc[j][3] = bf.y;
            } else { sc[j][2] = 0.f; sc[j][3] = 0.f; }
        }
        #pragma unroll
        for (int j = 0; j < 7; j++) {
            uint2 kk = *reinterpret_cast<const uint2*>(&Ks[buf][(j * 8 + g) * 8 + 2 * t4]);
            mma_f16_k16(sc[j], qh, kk.x, kk.y);
        }

        // ---- row max: local fp32 reduce, then packed fp16x2 quad shuffles
        float mx0 = rm0, mx1 = rm1;
        #pragma unroll
        for (int j = 0; j < 7; j++) {
            mx0 = fmaxf(mx0, fmaxf(sc[j][0], sc[j][1]));
            mx1 = fmaxf(mx1, fmaxf(sc[j][2], sc[j][3]));
        }
        {
            uint32_t mp = pack_h2(mx0, mx1);
            mp = hmax2(mp, __shfl_xor_sync(0xffffffffu, mp, 1));
            mp = hmax2(mp, __shfl_xor_sync(0xffffffffu, mp, 2));
            float2 mf = __half22float2(*reinterpret_cast<__half2*>(&mp));
            // fp16 rounding may round down by <=1ulp; bump to keep exp args <= ~0
            mx0 = mf.x; mx1 = mf.y;
        }

        float a0 = exp2fast(rm0 - mx0), a1 = exp2fast(rm1 - mx1);
        rl0 *= a0; rl1 *= a1; rm0 = mx0; rm1 = mx1;
        #pragma unroll
        for (int v = 0; v < 4; v++) {
            oc[v][0] *= a0; oc[v][1] *= a0;
            oc[v][2] *= a1; oc[v][3] *= a1;
        }

        uint32_t ph[7][2];
        float s0 = 0.f, s1 = 0.f;
        #pragma unroll
        for (int j = 0; j < 7; j++) {
            uint32_t dA = pack_h2(sc[j][0] - mx0, sc[j][1] - mx0);
            uint32_t dB = pack_h2(sc[j][2] - mx1, sc[j][3] - mx1);
            uint32_t pA = h2exp2(dA);
            uint32_t pB = h2exp2(dB);
            ph[j][0] = pA;
            ph[j][1] = pB;
            float2 fA = __half22float2(*reinterpret_cast<__half2*>(&pA));
            float2 fB = __half22float2(*reinterpret_cast<__half2*>(&pB));
            s0 += fA.x + fA.y;
            s1 += fB.x + fB.y;
        }
        s0 += __shfl_xor_sync(0xffffffffu, s0, 1);
        s0 += __shfl_xor_sync(0xffffffffu, s0, 2);
        s1 += __shfl_xor_sync(0xffffffffu, s1, 1);
        s1 += __shfl_xor_sync(0xffffffffu, s1, 2);
        rl0 += s0; rl1 += s1;

        #pragma unroll
        for (int jj = 0; jj < 3; jj++) {
            uint32_t pa[4] = { ph[2*jj][0], ph[2*jj][1], ph[2*jj+1][0], ph[2*jj+1][1] };
            #pragma unroll
            for (int v = 0; v < 4; v++) {
                uint2 vv = *reinterpret_cast<const uint2*>(
                    &Vs[buf][(v * 8 + g) * 40 + 8 * jj + 2 * t4]);
                mma_f16_k16(oc[v], pa, vv.x, vv.y);
            }
        }
        #pragma unroll
        for (int v = 0; v < 4; v++) {
            uint32_t vv = Vs[buf][(v * 8 + g) * 40 + 24 + 2 * t4];
            mma_f16_k8(oc[v], ph[6][0], ph[6][1], vv);
        }

        if (more) {
            int nb = buf ^ 1;
            Ks[nb][kRow * 8 + kphys] = combine_h2(ka0, ka1);
            if (kHi) Ks[nb][(kRow + 32) * 8 + kphys] = combine_h2(kb0, kb1);
            #pragma unroll
            for (int lp = 0; lp < 4; lp++) {
                int l = vl + 8 * lp;
                if (l < 28) Vs[nb][vd * 40 + ((l >> 3) << 3) + pperm(l & 7)] = vreg[lp];
            }
            __syncthreads();
        }
        buf ^= 1;
    }

    float inv0 = 1.f / rl0, inv1 = 1.f / rl1;
    #pragma unroll
    for (int v = 0; v < 4; v++) {
        #pragma unroll
        for (int e = 0; e < 2; e++) {
            int d = v * 8 + 2 * t4 + e;
            if (qA < 196)
                g_att[((size_t)b * 256 + h * 32 + d) * 196 + qA] =
                    __float2half(hardswish(oc[v][e] * inv0));
            if (qB < 196)
                g_att[((size_t)b * 256 + h * 32 + d) * 196 + qB] =
                    __float2half(hardswish(oc[v][2 + e] * inv1));
        }
    }
}

// ---------------- launch -----------------------------------------------------
extern "C" void kernel_launch(void* const* d_in, const int* in_sizes, int n_in,
                              void* d_out, int out_size)
{
    const float* x      = (const float*)d_in[0];
    const float* kv_w   = (const float*)d_in[1];
    const float* kv_g   = (const float*)d_in[2];
    const float* kv_b   = (const float*)d_in[3];
    const float* kv_m   = (const float*)d_in[4];
    const float* kv_v   = (const float*)d_in[5];
    const float* q_w    = (const float*)d_in[6];
    const float* q_g    = (const float*)d_in[7];
    const float* q_b    = (const float*)d_in[8];
    const float* q_m    = (const float*)d_in[9];
    const float* q_v    = (const float*)d_in[10];
    const float* proj_w = (const float*)d_in[11];
    const float* proj_g = (const float*)d_in[12];
    const float* proj_b = (const float*)d_in[13];
    const float* proj_m = (const float*)d_in[14];
    const float* proj_v = (const float*)d_in[15];
    const float* ab     = (const float*)d_in[16];
    const int*   idxs   = (const int*)  d_in[17];
    const int n_off = in_sizes[16] / 8;

    float* out = (float*)d_out;

    __half *p_kv, *p_q, *p_att;
    cudaGetSymbolAddress((void**)&p_kv,  g_kv);
    cudaGetSymbolAddress((void**)&p_q,   g_q);
    cudaGetSymbolAddress((void**)&p_att, g_att);

    // side stream + events (created once; host objects, no device allocations)
    static cudaStream_t s1 = nullptr;
    static cudaEvent_t evFork = nullptr, evJoin = nullptr;
    if (s1 == nullptr) {
        cudaStreamCreateWithFlags(&s1, cudaStreamNonBlocking);
        cudaEventCreateWithFlags(&evFork, cudaEventDisableTiming);
        cudaEventCreateWithFlags(&evJoin, cudaEventDisableTiming);
    }

    // ---- fork: gather + q GEMM on s1, kv GEMM on the main (capture) stream
    cudaEventRecord(evFork, 0);
    cudaStreamWaitEvent(s1, evFork, 0);

    bias_gather_kernel<<<dim3(196, 8), 392, 0, s1>>>(ab, idxs, n_off);
    conv_bn_hsw_tc_kernel<true, float, __half><<<dim3(1, 98), 256, 0, s1>>>(
        x, 256 * 784, 784, q_w, 256, q_g, q_b, q_m, q_v, p_q, 128, 196);
    cudaEventRecord(evJoin, s1);

    conv_bn_hsw_tc_kernel<false, float, __half><<<dim3(3, 392), 256>>>(
        x, 256 * 784, 784, kv_w, 256, kv_g, kv_b, kv_m, kv_v, p_kv, 384, 784);

    // ---- join, then attention + proj on the main stream
    cudaStreamWaitEvent(0, evJoin, 0);

    attention_tc_kernel<<<dim3(512, 2), 256>>>();

    conv_bn_hsw_tc_kernel<false, __half, float><<<dim3(4, 98), 256>>>(
        p_att, 256 * 196, 196, proj_w, 256, proj_g, proj_b, proj_m, proj_v, out, 512, 196);
}